// round 8
// baseline (speedup 1.0000x reference)
#include <cuda_runtime.h>

#define MAXF 8192
#define NT   256          // threads per block
#define TJ   256          // j columns per shared tile
#define RPB  512          // rows per block (2 per thread)
#define NWARP (NT/32)
#define NCTA 592          // 4 CTAs/SM x 148 SMs, single resident wave

typedef unsigned long long u64;

// Face data: 8 floats/face: [nx ny nz q][cx cy cz 0], q = 0.5 + |c|^2
__device__ __align__(16) float g_srcF[MAXF * 8];
__device__ __align__(16) float g_tarF[MAXF * 8];
__device__ __align__(16) float g_refF[MAXF * 8];
__device__ double g_acc;
__device__ unsigned int g_done;

// ---- f32x2 helpers ----------------------------------------------------------
#define F2FMA(d,a,b,c) asm("fma.rn.f32x2 %0, %1, %2, %3;" : "=l"(d) : "l"(a), "l"(b), "l"(c))
#define F2MUL(d,a,b)   asm("mul.rn.f32x2 %0, %1, %2;"     : "=l"(d) : "l"(a), "l"(b))
#define F2ADD(d,a,b)   asm("add.rn.f32x2 %0, %1, %2;"     : "=l"(d) : "l"(a), "l"(b))

__device__ __forceinline__ u64 pk2(float x, float y) {
    u64 r; asm("mov.b64 %0, {%1,%2};" : "=l"(r) : "f"(x), "f"(y)); return r;
}
__device__ __forceinline__ void upk2(float& x, float& y, u64 v) {
    asm("mov.b64 {%0,%1}, %2;" : "=f"(x), "=f"(y) : "l"(v));
}
__device__ __forceinline__ u64 rcp2(u64 v) {
    u64 r;
    asm("{\n\t"
        ".reg .f32 a, b;\n\t"
        "mov.b64 {a, b}, %1;\n\t"
        "rcp.approx.f32 a, a;\n\t"
        "rcp.approx.f32 b, b;\n\t"
        "mov.b64 %0, {a, b};\n\t"
        "}" : "=l"(r) : "l"(v));
    return r;
}

// ---------------------------------------------------------------------------
// Fused prep: blockIdx.y = 0 (src faces), 1 (tar faces), 2 (ref copy).
// Index dtype detected per block: little-endian int64 => all odd words zero.
// ---------------------------------------------------------------------------
__global__ void k_prep(const float* __restrict__ sv, const void* __restrict__ si,
                       int nVS, int nFS,
                       const float* __restrict__ tv, const void* __restrict__ ti,
                       int nVT, int nFT,
                       const float* __restrict__ rn, const float* __restrict__ rc,
                       int nFR) {
    int y = blockIdx.y;
    int f = blockIdx.x * blockDim.x + threadIdx.x;

    if (y == 2) {
        if (f == 0) { g_acc = 0.0; g_done = 0u; }
        if (f >= nFR) return;
        float nx = rn[3*f], ny = rn[3*f+1], nz = rn[3*f+2];
        float mx = rc[3*f], my = rc[3*f+1], mz = rc[3*f+2];
        float q = 0.5f + mx*mx + my*my + mz*mz;
        float4* o = (float4*)(g_refF + 8*f);
        o[0] = make_float4(nx, ny, nz, q);
        o[1] = make_float4(mx, my, mz, 0.0f);
        return;
    }

    const float* v   = y ? tv : sv;
    const void*  idr = y ? ti : si;
    int nV = y ? nVT : nVS;
    int nF = y ? nFT : nFS;
    float* out = y ? g_tarF : g_srcF;

    __shared__ unsigned int sOr;
    if (threadIdx.x == 0) sOr = 0u;
    __syncthreads();
    {
        const unsigned int* w = (const unsigned int*)idr;
        int probe = 2 * (int)threadIdx.x + 1;
        if (probe < 3 * nF) atomicOr(&sOr, w[probe]);
    }
    __syncthreads();
    bool idx64 = (sOr == 0u);

    if (f >= nF) return;

    long long i0, i1, i2;
    if (idx64) {
        const long long* idx = (const long long*)idr;
        i0 = idx[3*f]; i1 = idx[3*f+1]; i2 = idx[3*f+2];
    } else {
        const int* idx = (const int*)idr;
        i0 = idx[3*f]; i1 = idx[3*f+1]; i2 = idx[3*f+2];
    }
    if (i0 < 0) i0 = 0; if (i0 >= nV) i0 = nV - 1;
    if (i1 < 0) i1 = 0; if (i1 >= nV) i1 = nV - 1;
    if (i2 < 0) i2 = 0; if (i2 >= nV) i2 = nV - 1;

    float ax = v[3*i0], ay = v[3*i0+1], az = v[3*i0+2];
    float bx = v[3*i1], by = v[3*i1+1], bz = v[3*i1+2];
    float cx = v[3*i2], cy = v[3*i2+1], cz = v[3*i2+2];

    float ux = ax-bx, uy = ay-by, uz = az-bz;
    float wx = cx-bx, wy = cy-by, wz = cz-bz;

    float nx = 0.5f*(uy*wz - uz*wy);
    float ny = 0.5f*(uz*wx - ux*wz);
    float nz = 0.5f*(ux*wy - uy*wx);

    const float third = 1.0f/3.0f;
    float mx = (ax+bx+cx)*third, my = (ay+by+cy)*third, mz = (az+bz+cz)*third;
    float q = 0.5f + mx*mx + my*my + mz*mz;

    float4* o = (float4*)(out + 8*f);
    o[0] = make_float4(nx, ny, nz, q);
    o[1] = make_float4(mx, my, mz, 0.0f);
}

// ---------------------------------------------------------------------------
// Persistent pair kernel: one resident wave of NCTA CTAs, each loops over
// uniform 512x256 tile units with stride gridDim.x. Per-thread accumulation
// across units; single block reduction + atomic at the end.
// ---------------------------------------------------------------------------
__global__ void __launch_bounds__(NT, 4) k_pair(int nS, int nT, int nR,
                                                int o1, int o2, int o3, int o4, int o5,
                                                int total,
                                                float* __restrict__ outp) {
    __shared__ __align__(16) u64 sh[(TJ/2) * 8];
    float* shf = (float*)sh;

    float accT = 0.0f;

    for (int b = blockIdx.x; b < total; b += gridDim.x) {
        int region = (b >= o3) ? ((b >= o5) ? 5 : (b >= o4) ? 4 : 3)
                               : ((b >= o2) ? 2 : (b >= o1) ? 1 : 0);
        int local;
        const float *A, *B;
        float w;
        int nRows, nCols;
        switch (region) {
            case 0: A=g_srcF; B=g_srcF; w= 1.8f; nRows=nS; nCols=nS; local=b;      break;
            case 1: A=g_tarF; B=g_tarF; w= 1.8f; nRows=nT; nCols=nT; local=b-o1;   break;
            case 2: A=g_refF; B=g_refF; w= 2.0f; nRows=nR; nCols=nR; local=b-o2;   break;
            case 3: A=g_refF; B=g_srcF; w=-2.0f; nRows=nR; nCols=nS; local=b-o3;   break;
            case 4: A=g_refF; B=g_tarF; w=-2.0f; nRows=nR; nCols=nT; local=b-o4;   break;
            default:A=g_tarF; B=g_srcF; w=-1.6f; nRows=nT; nCols=nS; local=b-o5;   break;
        }
        bool sym = (region < 3);

        int J  = (nCols + TJ - 1) / TJ;          // j-tiles
        int Rb = (nRows + RPB - 1) / RPB;        // row-blocks

        int s2, tj;
        if (sym) {
            s2 = 0;
            int rem = local;
            while (s2 + 1 < Rb) {
                int cnt = J - 2*s2; if (cnt < 0) cnt = 0;
                if (rem < cnt) break;
                rem -= cnt; s2++;
            }
            tj = 2*s2 + rem;
        } else {
            s2 = local / J;
            tj = local - s2 * J;
        }

        const float4* A4 = (const float4*)A;
        const float4* B4 = (const float4*)B;

        int r0 = s2 * RPB + threadIdx.x;
        int r1 = r0 + TJ;
        u64 nR0[3], cR0[3], qR0, nR1[3], cR1[3], qR1;
        {
            float4 a0, a1;
            if (r0 < nRows) { a0 = A4[2*r0]; a1 = A4[2*r0+1]; }
            else { a0 = make_float4(0,0,0,0.5f); a1 = make_float4(0,0,0,0); }
            nR0[0]=pk2(a0.x,a0.x); nR0[1]=pk2(a0.y,a0.y); nR0[2]=pk2(a0.z,a0.z);
            cR0[0]=pk2(a1.x,a1.x); cR0[1]=pk2(a1.y,a1.y); cR0[2]=pk2(a1.z,a1.z);
            qR0 = pk2(a0.w,a0.w);
            if (r1 < nRows) { a0 = A4[2*r1]; a1 = A4[2*r1+1]; }
            else { a0 = make_float4(0,0,0,0.5f); a1 = make_float4(0,0,0,0); }
            nR1[0]=pk2(a0.x,a0.x); nR1[1]=pk2(a0.y,a0.y); nR1[2]=pk2(a0.z,a0.z);
            cR1[0]=pk2(a1.x,a1.x); cR1[1]=pk2(a1.y,a1.y); cR1[2]=pk2(a1.z,a1.z);
            qR1 = pk2(a0.w,a0.w);
        }

        __syncthreads();   // previous unit's readers done before refill
        {
            int t = threadIdx.x;
            int j = tj * TJ + t;
            int p = t >> 1, h = t & 1;
            float nx, ny, nz, q, cx, cy, cz;
            if (j < nCols) {
                float4 b0 = B4[2*j];
                float4 b1 = B4[2*j+1];
                nx = b0.x; ny = b0.y; nz = b0.z; q = b0.w;
                cx = -2.0f*b1.x; cy = -2.0f*b1.y; cz = -2.0f*b1.z;
            } else {
                nx = ny = nz = 0.0f; q = 0.5f; cx = cy = cz = 0.0f;
            }
            float* d = shf + p*16 + h;
            d[0] = nx; d[2] = ny; d[4] = nz; d[6] = q;
            d[8] = cx; d[10] = cy; d[12] = cz;
        }
        __syncthreads();

        u64 aT0 = 0ull, aT1 = 0ull;
        const ulonglong2* shv = (const ulonglong2*)sh;
        #pragma unroll 4
        for (int p = 0; p < TJ/2; ++p) {
            ulonglong2 v0 = shv[p*4 + 0];   // nx2 ny2
            ulonglong2 v1 = shv[p*4 + 1];   // nz2 q2
            ulonglong2 v2 = shv[p*4 + 2];   // csx2 csy2
            ulonglong2 v3 = shv[p*4 + 3];   // csz2 pad

            {   // row 0
                u64 nn, u, t;
                F2MUL(nn, nR0[0], v0.x);
                F2FMA(nn, nR0[1], v0.y, nn);
                F2FMA(nn, nR0[2], v1.x, nn);
                F2FMA(u, cR0[0], v2.x, v1.y);
                F2FMA(u, cR0[1], v2.y, u);
                F2FMA(u, cR0[2], v3.x, u);
                F2ADD(u, u, qR0);
                u64 r2 = rcp2(u);
                F2MUL(t, nn, r2);
                F2FMA(aT0, t, r2, aT0);
            }
            {   // row 1
                u64 nn, u, t;
                F2MUL(nn, nR1[0], v0.x);
                F2FMA(nn, nR1[1], v0.y, nn);
                F2FMA(nn, nR1[2], v1.x, nn);
                F2FMA(u, cR1[0], v2.x, v1.y);
                F2FMA(u, cR1[1], v2.y, u);
                F2FMA(u, cR1[2], v3.x, u);
                F2ADD(u, u, qR1);
                u64 r2 = rcp2(u);
                F2MUL(t, nn, r2);
                F2FMA(aT1, t, r2, aT1);
            }
        }

        float w0f = 1.0f, w1f = 1.0f;
        if (sym) {
            int s0 = 2*s2, s1 = s0 + 1;
            w0f = (tj == s0) ? 1.0f : 2.0f;                    // tj >= s0 by decode
            w1f = (tj < s1) ? 0.0f : ((tj == s1) ? 1.0f : 2.0f);
        }

        float a_, b_, c_, d_;
        upk2(a_, b_, aT0); upk2(c_, d_, aT1);
        accT += w * (w0f * (a_ + b_) + w1f * (c_ + d_));
    }

    // ---- one reduction + atomic per CTA ----
    #pragma unroll
    for (int o = 16; o; o >>= 1)
        accT += __shfl_xor_sync(0xffffffffu, accT, o);

    __shared__ float wsum[NWARP];
    int wid = threadIdx.x >> 5;
    if ((threadIdx.x & 31) == 0) wsum[wid] = accT;
    __syncthreads();
    if (threadIdx.x == 0) {
        float s = 0.0f;
        #pragma unroll
        for (int k = 0; k < NWARP; k++) s += wsum[k];
        atomicAdd(&g_acc, (double)s);
        __threadfence();
        unsigned int ticket = atomicAdd(&g_done, 1u);
        if (ticket == gridDim.x - 1u) outp[0] = (float)g_acc;
    }
}

// ---------------------------------------------------------------------------
static inline int units_sym(int n) {
    int Rb = (n + RPB - 1) / RPB;
    int J  = (n + TJ - 1) / TJ;
    int u = 0;
    for (int s2 = 0; s2 < Rb; ++s2) { int c = J - 2*s2; if (c < 0) c = 0; u += c; }
    return u;
}
static inline int units_full(int nr, int nc) {
    return ((nr + RPB - 1) / RPB) * ((nc + TJ - 1) / TJ);
}

extern "C" void kernel_launch(void* const* d_in, const int* in_sizes, int n_in,
                              void* d_out, int out_size) {
    const float* sv = (const float*)d_in[0];
    const void*  si = d_in[1];
    const float* tv = (const float*)d_in[2];
    const void*  ti = d_in[3];
    const float* rn = (const float*)d_in[4];
    const float* rc = (const float*)d_in[5];

    int VSn = in_sizes[0] / 3;
    int FSn = in_sizes[1] / 3;
    int VTn = in_sizes[2] / 3;
    int FTn = in_sizes[3] / 3;
    int FRn = in_sizes[4] / 3;

    int nMax = FSn > FTn ? FSn : FTn;
    if (FRn > nMax) nMax = FRn;

    dim3 pgrid((nMax + 255) / 256, 3, 1);
    k_prep<<<pgrid, 256>>>(sv, si, VSn, FSn, tv, ti, VTn, FTn, rn, rc, FRn);

    int u0 = units_sym(FSn);          // ss
    int u1 = units_sym(FTn);          // tt
    int u2 = units_sym(FRn);          // rr
    int u3 = units_full(FRn, FSn);    // rs
    int u4 = units_full(FRn, FTn);    // rt
    int u5 = units_full(FTn, FSn);    // ts

    int o1 = u0;
    int o2 = o1 + u1;
    int o3 = o2 + u2;
    int o4 = o3 + u3;
    int o5 = o4 + u4;
    int total = o5 + u5;

    int grid = NCTA < total ? NCTA : total;
    k_pair<<<grid, NT>>>(FSn, FTn, FRn, o1, o2, o3, o4, o5, total, (float*)d_out);
}

// round 9
// speedup vs baseline: 1.5823x; 1.5823x over previous
#include <cuda_runtime.h>

#define MAXF 8192
#define NT   128          // threads per block (4 warps)
#define TJ   256          // j columns per shared tile
#define RPB  256          // rows per block (2 per thread)
#define NWARP (NT/32)

typedef unsigned long long u64;

// Face data: 8 floats/face: [nx ny nz q][cx cy cz 0], q = 0.5 + |c|^2
__device__ __align__(16) float g_srcF[MAXF * 8];
__device__ __align__(16) float g_tarF[MAXF * 8];
__device__ __align__(16) float g_refF[MAXF * 8];
__device__ double g_acc;
__device__ unsigned int g_done;

// ---- f32x2 helpers ----------------------------------------------------------
#define F2FMA(d,a,b,c) asm("fma.rn.f32x2 %0, %1, %2, %3;" : "=l"(d) : "l"(a), "l"(b), "l"(c))
#define F2MUL(d,a,b)   asm("mul.rn.f32x2 %0, %1, %2;"     : "=l"(d) : "l"(a), "l"(b))
#define F2ADD(d,a,b)   asm("add.rn.f32x2 %0, %1, %2;"     : "=l"(d) : "l"(a), "l"(b))

__device__ __forceinline__ u64 pk2(float x, float y) {
    u64 r; asm("mov.b64 %0, {%1,%2};" : "=l"(r) : "f"(x), "f"(y)); return r;
}
__device__ __forceinline__ void upk2(float& x, float& y, u64 v) {
    asm("mov.b64 {%0,%1}, %2;" : "=f"(x), "=f"(y) : "l"(v));
}
__device__ __forceinline__ u64 rcp2(u64 v) {
    u64 r;
    asm("{\n\t"
        ".reg .f32 a, b;\n\t"
        "mov.b64 {a, b}, %1;\n\t"
        "rcp.approx.f32 a, a;\n\t"
        "rcp.approx.f32 b, b;\n\t"
        "mov.b64 %0, {a, b};\n\t"
        "}" : "=l"(r) : "l"(v));
    return r;
}

// ---------------------------------------------------------------------------
// Fused prep: blockIdx.y = 0 (src faces), 1 (tar faces), 2 (ref copy).
// Index dtype detected per block: little-endian int64 => all odd words zero.
// ---------------------------------------------------------------------------
__global__ void k_prep(const float* __restrict__ sv, const void* __restrict__ si,
                       int nVS, int nFS,
                       const float* __restrict__ tv, const void* __restrict__ ti,
                       int nVT, int nFT,
                       const float* __restrict__ rn, const float* __restrict__ rc,
                       int nFR) {
    int y = blockIdx.y;
    int f = blockIdx.x * blockDim.x + threadIdx.x;

    if (y == 2) {
        if (f == 0) { g_acc = 0.0; g_done = 0u; }
        if (f >= nFR) return;
        float nx = rn[3*f], ny = rn[3*f+1], nz = rn[3*f+2];
        float mx = rc[3*f], my = rc[3*f+1], mz = rc[3*f+2];
        float q = 0.5f + mx*mx + my*my + mz*mz;
        float4* o = (float4*)(g_refF + 8*f);
        o[0] = make_float4(nx, ny, nz, q);
        o[1] = make_float4(mx, my, mz, 0.0f);
        return;
    }

    const float* v   = y ? tv : sv;
    const void*  idr = y ? ti : si;
    int nV = y ? nVT : nVS;
    int nF = y ? nFT : nFS;
    float* out = y ? g_tarF : g_srcF;

    __shared__ unsigned int sOr;
    if (threadIdx.x == 0) sOr = 0u;
    __syncthreads();
    {
        const unsigned int* w = (const unsigned int*)idr;
        int probe = 2 * (int)threadIdx.x + 1;
        if (probe < 3 * nF) atomicOr(&sOr, w[probe]);
    }
    __syncthreads();
    bool idx64 = (sOr == 0u);

    if (f >= nF) return;

    long long i0, i1, i2;
    if (idx64) {
        const long long* idx = (const long long*)idr;
        i0 = idx[3*f]; i1 = idx[3*f+1]; i2 = idx[3*f+2];
    } else {
        const int* idx = (const int*)idr;
        i0 = idx[3*f]; i1 = idx[3*f+1]; i2 = idx[3*f+2];
    }
    if (i0 < 0) i0 = 0; if (i0 >= nV) i0 = nV - 1;
    if (i1 < 0) i1 = 0; if (i1 >= nV) i1 = nV - 1;
    if (i2 < 0) i2 = 0; if (i2 >= nV) i2 = nV - 1;

    float ax = v[3*i0], ay = v[3*i0+1], az = v[3*i0+2];
    float bx = v[3*i1], by = v[3*i1+1], bz = v[3*i1+2];
    float cx = v[3*i2], cy = v[3*i2+1], cz = v[3*i2+2];

    float ux = ax-bx, uy = ay-by, uz = az-bz;
    float wx = cx-bx, wy = cy-by, wz = cz-bz;

    float nx = 0.5f*(uy*wz - uz*wy);
    float ny = 0.5f*(uz*wx - ux*wz);
    float nz = 0.5f*(ux*wy - uy*wx);

    const float third = 1.0f/3.0f;
    float mx = (ax+bx+cx)*third, my = (ay+by+cy)*third, mz = (az+bz+cz)*third;
    float q = 0.5f + mx*mx + my*my + mz*mz;

    float4* o = (float4*)(out + 8*f);
    o[0] = make_float4(nx, ny, nz, q);
    o[1] = make_float4(mx, my, mz, 0.0f);
}

// ---------------------------------------------------------------------------
// Pair kernel: one CTA = one 256x256 tile unit. NT=128, 2 rows/thread
// (r, r+128 — both inside the same 256-row subtile => one weight per tile).
// ---------------------------------------------------------------------------
__global__ void __launch_bounds__(NT) k_pair(int nS, int nT, int nR,
                                             int o1, int o2, int o3, int o4, int o5,
                                             int total,
                                             float* __restrict__ outp) {
    int b = blockIdx.x;
    int region = (b >= o3) ? ((b >= o5) ? 5 : (b >= o4) ? 4 : 3)
                           : ((b >= o2) ? 2 : (b >= o1) ? 1 : 0);
    int local;
    const float *A, *B;
    float w;
    int nRows, nCols;
    switch (region) {
        case 0: A=g_srcF; B=g_srcF; w= 1.8f; nRows=nS; nCols=nS; local=b;      break;
        case 1: A=g_tarF; B=g_tarF; w= 1.8f; nRows=nT; nCols=nT; local=b-o1;   break;
        case 2: A=g_refF; B=g_refF; w= 2.0f; nRows=nR; nCols=nR; local=b-o2;   break;
        case 3: A=g_refF; B=g_srcF; w=-2.0f; nRows=nR; nCols=nS; local=b-o3;   break;
        case 4: A=g_refF; B=g_tarF; w=-2.0f; nRows=nR; nCols=nT; local=b-o4;   break;
        default:A=g_tarF; B=g_srcF; w=-1.6f; nRows=nT; nCols=nS; local=b-o5;   break;
    }
    bool sym = (region < 3);

    int J  = (nCols + TJ - 1) / TJ;          // j-tiles
    int Rb = (nRows + RPB - 1) / RPB;        // row-blocks

    int s2, tj;                              // row-block, j-tile indices
    if (sym) {
        s2 = 0;
        int rem = local;
        while (s2 + 1 < Rb) {
            int cnt = J - s2; if (cnt < 0) cnt = 0;
            if (rem < cnt) break;
            rem -= cnt; s2++;
        }
        tj = s2 + rem;
    } else {
        s2 = local / J;
        tj = local - s2 * J;
    }

    __shared__ __align__(16) u64 sh[(TJ/2) * 8];
    float* shf = (float*)sh;

    const float4* A4 = (const float4*)A;
    const float4* B4 = (const float4*)B;

    int r0 = s2 * RPB + threadIdx.x;
    int r1 = r0 + NT;                        // same 256-row subtile
    u64 nR0[3], cR0[3], qR0, nR1[3], cR1[3], qR1;
    {
        float4 a0, a1;
        if (r0 < nRows) { a0 = A4[2*r0]; a1 = A4[2*r0+1]; }
        else { a0 = make_float4(0,0,0,0.5f); a1 = make_float4(0,0,0,0); }
        nR0[0]=pk2(a0.x,a0.x); nR0[1]=pk2(a0.y,a0.y); nR0[2]=pk2(a0.z,a0.z);
        cR0[0]=pk2(a1.x,a1.x); cR0[1]=pk2(a1.y,a1.y); cR0[2]=pk2(a1.z,a1.z);
        qR0 = pk2(a0.w,a0.w);
        if (r1 < nRows) { a0 = A4[2*r1]; a1 = A4[2*r1+1]; }
        else { a0 = make_float4(0,0,0,0.5f); a1 = make_float4(0,0,0,0); }
        nR1[0]=pk2(a0.x,a0.x); nR1[1]=pk2(a0.y,a0.y); nR1[2]=pk2(a0.z,a0.z);
        cR1[0]=pk2(a1.x,a1.x); cR1[1]=pk2(a1.y,a1.y); cR1[2]=pk2(a1.z,a1.z);
        qR1 = pk2(a0.w,a0.w);
    }

    // ---- shared fill: thread t loads j-pair (2t, 2t+1) into slot t ----
    {
        int t = threadIdx.x;
        int j0 = tj * TJ + 2*t;
        float nxa, nya, nza, qa, cxa, cya, cza;
        float nxb, nyb, nzb, qb, cxb, cyb, czb;
        if (j0 < nCols) {
            float4 b0 = B4[2*j0], b1 = B4[2*j0+1];
            nxa=b0.x; nya=b0.y; nza=b0.z; qa=b0.w;
            cxa=-2.0f*b1.x; cya=-2.0f*b1.y; cza=-2.0f*b1.z;
        } else { nxa=nya=nza=0.f; qa=0.5f; cxa=cya=cza=0.f; }
        if (j0 + 1 < nCols) {
            float4 b0 = B4[2*(j0+1)], b1 = B4[2*(j0+1)+1];
            nxb=b0.x; nyb=b0.y; nzb=b0.z; qb=b0.w;
            cxb=-2.0f*b1.x; cyb=-2.0f*b1.y; czb=-2.0f*b1.z;
        } else { nxb=nyb=nzb=0.f; qb=0.5f; cxb=cyb=czb=0.f; }
        float* d = shf + t*16;
        d[0]=nxa; d[1]=nxb; d[2]=nya; d[3]=nyb;
        d[4]=nza; d[5]=nzb; d[6]=qa;  d[7]=qb;
        d[8]=cxa; d[9]=cxb; d[10]=cya; d[11]=cyb;
        d[12]=cza; d[13]=czb;
    }
    __syncthreads();

    u64 aT0 = 0ull, aT1 = 0ull;
    const ulonglong2* shv = (const ulonglong2*)sh;
    #pragma unroll 4
    for (int p = 0; p < TJ/2; ++p) {
        ulonglong2 v0 = shv[p*4 + 0];   // nx2 ny2
        ulonglong2 v1 = shv[p*4 + 1];   // nz2 q2
        ulonglong2 v2 = shv[p*4 + 2];   // csx2 csy2
        ulonglong2 v3 = shv[p*4 + 3];   // csz2 pad

        {   // row 0
            u64 nn, u, t;
            F2MUL(nn, nR0[0], v0.x);
            F2FMA(nn, nR0[1], v0.y, nn);
            F2FMA(nn, nR0[2], v1.x, nn);
            F2FMA(u, cR0[0], v2.x, v1.y);
            F2FMA(u, cR0[1], v2.y, u);
            F2FMA(u, cR0[2], v3.x, u);
            F2ADD(u, u, qR0);
            u64 r2 = rcp2(u);
            F2MUL(t, nn, r2);
            F2FMA(aT0, t, r2, aT0);
        }
        {   // row 1
            u64 nn, u, t;
            F2MUL(nn, nR1[0], v0.x);
            F2FMA(nn, nR1[1], v0.y, nn);
            F2FMA(nn, nR1[2], v1.x, nn);
            F2FMA(u, cR1[0], v2.x, v1.y);
            F2FMA(u, cR1[1], v2.y, u);
            F2FMA(u, cR1[2], v3.x, u);
            F2ADD(u, u, qR1);
            u64 r2 = rcp2(u);
            F2MUL(t, nn, r2);
            F2FMA(aT1, t, r2, aT1);
        }
    }

    float wt = 1.0f;
    if (sym) wt = (tj == s2) ? 1.0f : 2.0f;   // tj >= s2 by decode

    float a_, b_, c_, d_;
    upk2(a_, b_, aT0); upk2(c_, d_, aT1);
    float acc = w * wt * ((a_ + b_) + (c_ + d_));

    #pragma unroll
    for (int o = 16; o; o >>= 1)
        acc += __shfl_xor_sync(0xffffffffu, acc, o);

    __shared__ float wsum[NWARP];
    int wid = threadIdx.x >> 5;
    if ((threadIdx.x & 31) == 0) wsum[wid] = acc;
    __syncthreads();
    if (threadIdx.x == 0) {
        float s = 0.0f;
        #pragma unroll
        for (int k = 0; k < NWARP; k++) s += wsum[k];
        atomicAdd(&g_acc, (double)s);
        __threadfence();
        unsigned int ticket = atomicAdd(&g_done, 1u);
        if (ticket == (unsigned int)total - 1u) outp[0] = (float)g_acc;
    }
}

// ---------------------------------------------------------------------------
static inline int units_sym(int n) {
    int Rb = (n + RPB - 1) / RPB;
    int J  = (n + TJ - 1) / TJ;
    int u = 0;
    for (int s2 = 0; s2 < Rb; ++s2) { int c = J - s2; if (c < 0) c = 0; u += c; }
    return u;
}
static inline int units_full(int nr, int nc) {
    return ((nr + RPB - 1) / RPB) * ((nc + TJ - 1) / TJ);
}

extern "C" void kernel_launch(void* const* d_in, const int* in_sizes, int n_in,
                              void* d_out, int out_size) {
    const float* sv = (const float*)d_in[0];
    const void*  si = d_in[1];
    const float* tv = (const float*)d_in[2];
    const void*  ti = d_in[3];
    const float* rn = (const float*)d_in[4];
    const float* rc = (const float*)d_in[5];

    int VSn = in_sizes[0] / 3;
    int FSn = in_sizes[1] / 3;
    int VTn = in_sizes[2] / 3;
    int FTn = in_sizes[3] / 3;
    int FRn = in_sizes[4] / 3;

    int nMax = FSn > FTn ? FSn : FTn;
    if (FRn > nMax) nMax = FRn;

    dim3 pgrid((nMax + 255) / 256, 3, 1);
    k_prep<<<pgrid, 256>>>(sv, si, VSn, FSn, tv, ti, VTn, FTn, rn, rc, FRn);

    int u0 = units_sym(FSn);          // ss
    int u1 = units_sym(FTn);          // tt
    int u2 = units_sym(FRn);          // rr
    int u3 = units_full(FRn, FSn);    // rs
    int u4 = units_full(FRn, FTn);    // rt
    int u5 = units_full(FTn, FSn);    // ts

    int o1 = u0;
    int o2 = o1 + u1;
    int o3 = o2 + u2;
    int o4 = o3 + u3;
    int o5 = o4 + u4;
    int total = o5 + u5;

    k_pair<<<total, NT>>>(FSn, FTn, FRn, o1, o2, o3, o4, o5, total, (float*)d_out);
}

// round 10
// speedup vs baseline: 1.8172x; 1.1484x over previous
#include <cuda_runtime.h>

#define MAXF 8192
#define NT   256          // threads per block
#define TJ   256          // j columns per shared tile
#define RPB  512          // rows per block (2 per thread)
#define NWARP (NT/32)

typedef unsigned long long u64;

// Face data: 8 floats/face: [nx ny nz q][cx cy cz 0], q = 0.5 + |c|^2
__device__ __align__(16) float g_srcF[MAXF * 8];
__device__ __align__(16) float g_tarF[MAXF * 8];
__device__ __align__(16) float g_refF[MAXF * 8];
__device__ double g_acc;
__device__ unsigned int g_done;

__device__ __forceinline__ u64 pk2(float x, float y) {
    u64 r; asm("mov.b64 %0, {%1,%2};" : "=l"(r) : "f"(x), "f"(y)); return r;
}
__device__ __forceinline__ void upk2(float& x, float& y, u64 v) {
    asm("mov.b64 {%0,%1}, %2;" : "=f"(x), "=f"(y) : "l"(v));
}

// One fused 4-pair body (2 rows x 2 j-columns x f32x2). Single asm block so
// ptxas binds all temporaries directly (no inter-asm marshaling MOVs).
// Paired reciprocal: r = rcp(u0*u1), 1/u0 = r*u1, 1/u1 = r*u0  (2 MUFU not 4).
#define PAIR4(sa)                                                           \
    asm("{\n\t"                                                             \
        ".reg .b64 vnx,vny,vnz,vq,vcx,vcy,vcz,nn0,nn1,u0,u1,pr,iv0,iv1,t0,t1;\n\t" \
        ".reg .f32 pa,pb;\n\t"                                              \
        "ld.shared.v2.b64 {vnx,vny}, [%16+0];\n\t"                          \
        "ld.shared.v2.b64 {vnz,vq},  [%16+16];\n\t"                         \
        "ld.shared.v2.b64 {vcx,vcy}, [%16+32];\n\t"                         \
        "ld.shared.b64    vcz,       [%16+48];\n\t"                         \
        "mul.rn.f32x2 nn0, %2, vnx;\n\t"                                    \
        "mul.rn.f32x2 nn1, %9, vnx;\n\t"                                    \
        "fma.rn.f32x2 nn0, %3, vny, nn0;\n\t"                               \
        "fma.rn.f32x2 nn1, %10, vny, nn1;\n\t"                              \
        "fma.rn.f32x2 nn0, %4, vnz, nn0;\n\t"                               \
        "fma.rn.f32x2 nn1, %11, vnz, nn1;\n\t"                              \
        "fma.rn.f32x2 u0, %5, vcx, vq;\n\t"                                 \
        "fma.rn.f32x2 u1, %12, vcx, vq;\n\t"                                \
        "fma.rn.f32x2 u0, %6, vcy, u0;\n\t"                                 \
        "fma.rn.f32x2 u1, %13, vcy, u1;\n\t"                                \
        "fma.rn.f32x2 u0, %7, vcz, u0;\n\t"                                 \
        "fma.rn.f32x2 u1, %14, vcz, u1;\n\t"                                \
        "add.rn.f32x2 u0, u0, %8;\n\t"                                      \
        "add.rn.f32x2 u1, u1, %15;\n\t"                                     \
        "mul.rn.f32x2 pr, u0, u1;\n\t"                                      \
        "mov.b64 {pa,pb}, pr;\n\t"                                          \
        "rcp.approx.f32 pa, pa;\n\t"                                        \
        "rcp.approx.f32 pb, pb;\n\t"                                        \
        "mov.b64 pr, {pa,pb};\n\t"                                          \
        "mul.rn.f32x2 iv0, pr, u1;\n\t"                                     \
        "mul.rn.f32x2 iv1, pr, u0;\n\t"                                     \
        "mul.rn.f32x2 t0, nn0, iv0;\n\t"                                    \
        "mul.rn.f32x2 t1, nn1, iv1;\n\t"                                    \
        "fma.rn.f32x2 %0, t0, iv0, %0;\n\t"                                 \
        "fma.rn.f32x2 %1, t1, iv1, %1;\n\t"                                 \
        "}"                                                                 \
        : "+l"(aT0), "+l"(aT1)                                              \
        : "l"(nR0x), "l"(nR0y), "l"(nR0z), "l"(cR0x), "l"(cR0y), "l"(cR0z), "l"(qR0), \
          "l"(nR1x), "l"(nR1y), "l"(nR1z), "l"(cR1x), "l"(cR1y), "l"(cR1z), "l"(qR1), \
          "r"(sa)                                                           \
        : "memory")

// ---------------------------------------------------------------------------
// Fused prep: blockIdx.y = 0 (src faces), 1 (tar faces), 2 (ref copy).
// Index dtype detected per block: little-endian int64 => all odd words zero.
// ---------------------------------------------------------------------------
__global__ void k_prep(const float* __restrict__ sv, const void* __restrict__ si,
                       int nVS, int nFS,
                       const float* __restrict__ tv, const void* __restrict__ ti,
                       int nVT, int nFT,
                       const float* __restrict__ rn, const float* __restrict__ rc,
                       int nFR) {
    int y = blockIdx.y;
    int f = blockIdx.x * blockDim.x + threadIdx.x;

    if (y == 2) {
        if (f == 0) { g_acc = 0.0; g_done = 0u; }
        if (f >= nFR) return;
        float nx = rn[3*f], ny = rn[3*f+1], nz = rn[3*f+2];
        float mx = rc[3*f], my = rc[3*f+1], mz = rc[3*f+2];
        float q = 0.5f + mx*mx + my*my + mz*mz;
        float4* o = (float4*)(g_refF + 8*f);
        o[0] = make_float4(nx, ny, nz, q);
        o[1] = make_float4(mx, my, mz, 0.0f);
        return;
    }

    const float* v   = y ? tv : sv;
    const void*  idr = y ? ti : si;
    int nV = y ? nVT : nVS;
    int nF = y ? nFT : nFS;
    float* out = y ? g_tarF : g_srcF;

    __shared__ unsigned int sOr;
    if (threadIdx.x == 0) sOr = 0u;
    __syncthreads();
    {
        const unsigned int* w = (const unsigned int*)idr;
        int probe = 2 * (int)threadIdx.x + 1;
        if (probe < 3 * nF) atomicOr(&sOr, w[probe]);
    }
    __syncthreads();
    bool idx64 = (sOr == 0u);

    if (f >= nF) return;

    long long i0, i1, i2;
    if (idx64) {
        const long long* idx = (const long long*)idr;
        i0 = idx[3*f]; i1 = idx[3*f+1]; i2 = idx[3*f+2];
    } else {
        const int* idx = (const int*)idr;
        i0 = idx[3*f]; i1 = idx[3*f+1]; i2 = idx[3*f+2];
    }
    if (i0 < 0) i0 = 0; if (i0 >= nV) i0 = nV - 1;
    if (i1 < 0) i1 = 0; if (i1 >= nV) i1 = nV - 1;
    if (i2 < 0) i2 = 0; if (i2 >= nV) i2 = nV - 1;

    float ax = v[3*i0], ay = v[3*i0+1], az = v[3*i0+2];
    float bx = v[3*i1], by = v[3*i1+1], bz = v[3*i1+2];
    float cx = v[3*i2], cy = v[3*i2+1], cz = v[3*i2+2];

    float ux = ax-bx, uy = ay-by, uz = az-bz;
    float wx = cx-bx, wy = cy-by, wz = cz-bz;

    float nx = 0.5f*(uy*wz - uz*wy);
    float ny = 0.5f*(uz*wx - ux*wz);
    float nz = 0.5f*(ux*wy - uy*wx);

    const float third = 1.0f/3.0f;
    float mx = (ax+bx+cx)*third, my = (ay+by+cy)*third, mz = (az+bz+cz)*third;
    float q = 0.5f + mx*mx + my*my + mz*mz;

    float4* o = (float4*)(out + 8*f);
    o[0] = make_float4(nx, ny, nz, q);
    o[1] = make_float4(mx, my, mz, 0.0f);
}

// ---------------------------------------------------------------------------
// Pair kernel, flattened uniform work units: one CTA = one 512x256 tile.
// ---------------------------------------------------------------------------
__global__ void __launch_bounds__(NT) k_pair(int nS, int nT, int nR,
                                             int o1, int o2, int o3, int o4, int o5,
                                             int total,
                                             float* __restrict__ outp) {
    int b = blockIdx.x;
    int region = (b >= o3) ? ((b >= o5) ? 5 : (b >= o4) ? 4 : 3)
                           : ((b >= o2) ? 2 : (b >= o1) ? 1 : 0);
    int local;
    const float *A, *B;
    float w;
    int nRows, nCols;
    switch (region) {
        case 0: A=g_srcF; B=g_srcF; w= 1.8f; nRows=nS; nCols=nS; local=b;      break;
        case 1: A=g_tarF; B=g_tarF; w= 1.8f; nRows=nT; nCols=nT; local=b-o1;   break;
        case 2: A=g_refF; B=g_refF; w= 2.0f; nRows=nR; nCols=nR; local=b-o2;   break;
        case 3: A=g_refF; B=g_srcF; w=-2.0f; nRows=nR; nCols=nS; local=b-o3;   break;
        case 4: A=g_refF; B=g_tarF; w=-2.0f; nRows=nR; nCols=nT; local=b-o4;   break;
        default:A=g_tarF; B=g_srcF; w=-1.6f; nRows=nT; nCols=nS; local=b-o5;   break;
    }
    bool sym = (region < 3);

    int J  = (nCols + TJ - 1) / TJ;          // j-tiles
    int Rb = (nRows + RPB - 1) / RPB;        // row-blocks

    int s2, tj;                              // row-block, j-tile indices
    if (sym) {
        s2 = 0;
        int rem = local;
        while (s2 + 1 < Rb) {
            int cnt = J - 2*s2; if (cnt < 0) cnt = 0;
            if (rem < cnt) break;
            rem -= cnt; s2++;
        }
        tj = 2*s2 + rem;
    } else {
        s2 = local / J;
        tj = local - s2 * J;
    }

    __shared__ __align__(16) u64 sh[(TJ/2) * 8];
    float* shf = (float*)sh;

    const float4* A4 = (const float4*)A;
    const float4* B4 = (const float4*)B;

    int r0 = s2 * RPB + threadIdx.x;
    int r1 = r0 + TJ;
    u64 nR0x,nR0y,nR0z,cR0x,cR0y,cR0z,qR0;
    u64 nR1x,nR1y,nR1z,cR1x,cR1y,cR1z,qR1;
    {
        float4 a0, a1;
        if (r0 < nRows) { a0 = A4[2*r0]; a1 = A4[2*r0+1]; }
        else { a0 = make_float4(0,0,0,0.5f); a1 = make_float4(0,0,0,0); }
        nR0x=pk2(a0.x,a0.x); nR0y=pk2(a0.y,a0.y); nR0z=pk2(a0.z,a0.z);
        cR0x=pk2(a1.x,a1.x); cR0y=pk2(a1.y,a1.y); cR0z=pk2(a1.z,a1.z);
        qR0 = pk2(a0.w,a0.w);
        if (r1 < nRows) { a0 = A4[2*r1]; a1 = A4[2*r1+1]; }
        else { a0 = make_float4(0,0,0,0.5f); a1 = make_float4(0,0,0,0); }
        nR1x=pk2(a0.x,a0.x); nR1y=pk2(a0.y,a0.y); nR1z=pk2(a0.z,a0.z);
        cR1x=pk2(a1.x,a1.x); cR1y=pk2(a1.y,a1.y); cR1z=pk2(a1.z,a1.z);
        qR1 = pk2(a0.w,a0.w);
    }

    // ---- shared fill (one tile) ----
    {
        int t = threadIdx.x;
        int j = tj * TJ + t;
        int p = t >> 1, h = t & 1;
        float nx, ny, nz, q, cx, cy, cz;
        if (j < nCols) {
            float4 b0 = B4[2*j];
            float4 b1 = B4[2*j+1];
            nx = b0.x; ny = b0.y; nz = b0.z; q = b0.w;
            cx = -2.0f*b1.x; cy = -2.0f*b1.y; cz = -2.0f*b1.z;
        } else {
            nx = ny = nz = 0.0f; q = 0.5f; cx = cy = cz = 0.0f;
        }
        float* d = shf + p*16 + h;
        d[0] = nx; d[2] = ny; d[4] = nz; d[6] = q;
        d[8] = cx; d[10] = cy; d[12] = cz;
    }
    __syncthreads();

    u64 aT0 = 0ull, aT1 = 0ull;
    unsigned int sbase = (unsigned int)__cvta_generic_to_shared(sh);
    #pragma unroll 4
    for (int p = 0; p < TJ/2; ++p) {
        unsigned int sa = sbase + (unsigned int)(p * 64);
        PAIR4(sa);
    }

    float w0f = 1.0f, w1f = 1.0f;
    if (sym) {
        int s0 = 2*s2, s1 = s0 + 1;
        w0f = (tj == s0) ? 1.0f : 2.0f;                       // tj >= s0 by decode
        w1f = (tj < s1) ? 0.0f : ((tj == s1) ? 1.0f : 2.0f);
    }

    float a_, b_, c_, d_;
    upk2(a_, b_, aT0); upk2(c_, d_, aT1);
    float acc = w * (w0f * (a_ + b_) + w1f * (c_ + d_));

    #pragma unroll
    for (int o = 16; o; o >>= 1)
        acc += __shfl_xor_sync(0xffffffffu, acc, o);

    __shared__ float wsum[NWARP];
    int wid = threadIdx.x >> 5;
    if ((threadIdx.x & 31) == 0) wsum[wid] = acc;
    __syncthreads();
    if (threadIdx.x == 0) {
        float s = 0.0f;
        #pragma unroll
        for (int k = 0; k < NWARP; k++) s += wsum[k];
        atomicAdd(&g_acc, (double)s);
        __threadfence();
        unsigned int ticket = atomicAdd(&g_done, 1u);
        if (ticket == (unsigned int)total - 1u) outp[0] = (float)g_acc;
    }
}

// ---------------------------------------------------------------------------
static inline int units_sym(int n) {
    int Rb = (n + RPB - 1) / RPB;
    int J  = (n + TJ - 1) / TJ;
    int u = 0;
    for (int s2 = 0; s2 < Rb; ++s2) { int c = J - 2*s2; if (c < 0) c = 0; u += c; }
    return u;
}
static inline int units_full(int nr, int nc) {
    return ((nr + RPB - 1) / RPB) * ((nc + TJ - 1) / TJ);
}

extern "C" void kernel_launch(void* const* d_in, const int* in_sizes, int n_in,
                              void* d_out, int out_size) {
    const float* sv = (const float*)d_in[0];
    const void*  si = d_in[1];
    const float* tv = (const float*)d_in[2];
    const void*  ti = d_in[3];
    const float* rn = (const float*)d_in[4];
    const float* rc = (const float*)d_in[5];

    int VSn = in_sizes[0] / 3;
    int FSn = in_sizes[1] / 3;
    int VTn = in_sizes[2] / 3;
    int FTn = in_sizes[3] / 3;
    int FRn = in_sizes[4] / 3;

    int nMax = FSn > FTn ? FSn : FTn;
    if (FRn > nMax) nMax = FRn;

    dim3 pgrid((nMax + 255) / 256, 3, 1);
    k_prep<<<pgrid, 256>>>(sv, si, VSn, FSn, tv, ti, VTn, FTn, rn, rc, FRn);

    int u0 = units_sym(FSn);          // ss
    int u1 = units_sym(FTn);          // tt
    int u2 = units_sym(FRn);          // rr
    int u3 = units_full(FRn, FSn);    // rs
    int u4 = units_full(FRn, FTn);    // rt
    int u5 = units_full(FTn, FSn);    // ts

    int o1 = u0;
    int o2 = o1 + u1;
    int o3 = o2 + u2;
    int o4 = o3 + u3;
    int o5 = o4 + u4;
    int total = o5 + u5;

    k_pair<<<total, NT>>>(FSn, FTn, FRn, o1, o2, o3, o4, o5, total, (float*)d_out);
}